// round 7
// baseline (speedup 1.0000x reference)
#include <cuda_runtime.h>
#include <cuda_fp16.h>

// 2-layer GCN: x[50000,64], edge_index[2,800000], W1[64,64], b1[64],
// W2[64,16], b2[16] -> out[50000,16] f32.
//
// R6 @133.6us. R7: h1/h2 stored fp16 (halves gather traffic; fp32 accum),
// agg1 4 edges/warp-iter, agg2 16 edges/warp-iter, CSR build with 4
// edges/thread for atomic ILP. CSR-by-dst + gather agg, no float atomics.

#define NN 50000
#define FIN 64
#define HID 64
#define NCLS 16
#define EMAX 800000

__device__ int    g_is32;            // 1 if edge_index is int32
__device__ int    g_cnt[NN];         // in-degree histogram (by dst)
__device__ int    g_pos[NN];         // scan: start offsets; after fill: end offsets
__device__ int    g_esrc[EMAX];      // src node per CSR slot
__device__ __half g_h1h[NN * HID];   // fp16 (x@W1) * dinv[row]
__device__ float  g_act1[NN * HID];  // fp32 relu layer-1 output
__device__ __half g_h2h[NN * NCLS];  // fp16 (act1@W2) * dinv[row]

__device__ __forceinline__ int clampn(int v) {
    if (v < 0) v = 0;
    if (v >= NN) v = NN - 1;
    return v;
}
__device__ __forceinline__ int load_idx(const void* ei, int i, int is32) {
    int v;
    if (is32) v = ((const int*)ei)[i];
    else      v = (int)((const long long*)ei)[i];
    return clampn(v);
}

// ---- zero histogram + detect dtype (int64-read of int32 pairs leaves [0,NN)) ----
__global__ void k_zero_detect(const long long* __restrict__ ei, int n) {
    int i = blockIdx.x * blockDim.x + threadIdx.x;
    if (i < n) g_cnt[i] = 0;
    if (i == 0) {
        int bad = 0;
#pragma unroll
        for (int j = 0; j < 64; j++) {
            long long v = ei[j];
            if (v < 0 || v >= NN) bad = 1;
        }
        g_is32 = bad;
    }
}

// ---- histogram of dst: 4 edges per thread for atomic ILP ----
__global__ void k_hist(const void* __restrict__ ei, int E) {
    int base = (blockIdx.x * blockDim.x + threadIdx.x) * 4;
    if (base >= E) return;
    int is32 = g_is32;
    if (base + 4 <= E) {
        int d0, d1, d2, d3;
        if (is32) {
            int4 v = *(const int4*)((const int*)ei + E + base);
            d0 = clampn(v.x); d1 = clampn(v.y); d2 = clampn(v.z); d3 = clampn(v.w);
        } else {
            longlong2 v0 = *(const longlong2*)((const long long*)ei + E + base);
            longlong2 v1 = *(const longlong2*)((const long long*)ei + E + base + 2);
            d0 = clampn((int)v0.x); d1 = clampn((int)v0.y);
            d2 = clampn((int)v1.x); d3 = clampn((int)v1.y);
        }
        atomicAdd(&g_cnt[d0], 1);
        atomicAdd(&g_cnt[d1], 1);
        atomicAdd(&g_cnt[d2], 1);
        atomicAdd(&g_cnt[d3], 1);
    } else {
        for (int e = base; e < E; e++)
            atomicAdd(&g_cnt[load_idx(ei, E + e, is32)], 1);
    }
}

// ---- single-block exclusive scan of g_cnt -> g_pos (start offsets) ----
__global__ void k_scan(int n) {
    __shared__ int partial[1024];
    int t = threadIdx.x;
    int chunk = (n + 1023) / 1024;
    int lo = t * chunk;
    int hi = lo + chunk; if (hi > n) hi = n;
    if (lo > n) lo = n;
    int s = 0;
    for (int i = lo; i < hi; i++) s += g_cnt[i];
    partial[t] = s;
    __syncthreads();
    for (int d = 1; d < 1024; d <<= 1) {
        int v = (t >= d) ? partial[t - d] : 0;
        __syncthreads();
        partial[t] += v;
        __syncthreads();
    }
    int base = (t == 0) ? 0 : partial[t - 1];
    for (int i = lo; i < hi; i++) {
        int c = g_cnt[i];
        g_pos[i] = base;
        base += c;
    }
}

// ---- fill CSR: 4 edges per thread (after: g_pos[d] = end offset) ----
__global__ void k_fill(const void* __restrict__ ei, int E) {
    int base = (blockIdx.x * blockDim.x + threadIdx.x) * 4;
    if (base >= E) return;
    int is32 = g_is32;
    if (base + 4 <= E) {
        int s0, s1, s2, s3, d0, d1, d2, d3;
        if (is32) {
            int4 sv = *(const int4*)((const int*)ei + base);
            int4 dv = *(const int4*)((const int*)ei + E + base);
            s0 = clampn(sv.x); s1 = clampn(sv.y); s2 = clampn(sv.z); s3 = clampn(sv.w);
            d0 = clampn(dv.x); d1 = clampn(dv.y); d2 = clampn(dv.z); d3 = clampn(dv.w);
        } else {
            const long long* p = (const long long*)ei;
            longlong2 sa = *(const longlong2*)(p + base);
            longlong2 sb = *(const longlong2*)(p + base + 2);
            longlong2 da = *(const longlong2*)(p + E + base);
            longlong2 db = *(const longlong2*)(p + E + base + 2);
            s0 = clampn((int)sa.x); s1 = clampn((int)sa.y);
            s2 = clampn((int)sb.x); s3 = clampn((int)sb.y);
            d0 = clampn((int)da.x); d1 = clampn((int)da.y);
            d2 = clampn((int)db.x); d3 = clampn((int)db.y);
        }
        int p0 = atomicAdd(&g_pos[d0], 1);
        int p1 = atomicAdd(&g_pos[d1], 1);
        int p2 = atomicAdd(&g_pos[d2], 1);
        int p3 = atomicAdd(&g_pos[d3], 1);
        if (p0 >= 0 && p0 < EMAX) g_esrc[p0] = s0;
        if (p1 >= 0 && p1 < EMAX) g_esrc[p1] = s1;
        if (p2 >= 0 && p2 < EMAX) g_esrc[p2] = s2;
        if (p3 >= 0 && p3 < EMAX) g_esrc[p3] = s3;
    } else {
        for (int e = base; e < E; e++) {
            int s = load_idx(ei, e, is32);
            int d = load_idx(ei, E + e, is32);
            int p = atomicAdd(&g_pos[d], 1);
            if (p >= 0 && p < EMAX) g_esrc[p] = s;
        }
    }
}

// ---- GEMM1: h1h[r,:] = fp16( (x[r,:] @ W1) * rsqrt(deg[r]+1) ) ----
__global__ void k_gemm1(const float* __restrict__ x, const float* __restrict__ W,
                        int n) {
    __shared__ float Ws[FIN * HID];
    __shared__ __align__(16) float xs[32][FIN];
    int t = threadIdx.x;
    for (int i = t; i < (FIN * HID) / 4; i += 256)
        ((float4*)Ws)[i] = ((const float4*)W)[i];
    int row0 = blockIdx.x * 32;
    if (row0 + 32 <= n) {
        for (int i = t; i < (32 * FIN) / 4; i += 256)
            ((float4*)xs)[i] = ((const float4*)(x + row0 * FIN))[i];
    } else {
        for (int i = t; i < 32 * FIN; i += 256) {
            int r = i >> 6, k = i & 63;
            int gr = row0 + r;
            xs[r][k] = (gr < n) ? x[gr * FIN + k] : 0.0f;
        }
    }
    __syncthreads();

    int c = t & 63;
    int rbase = t >> 6;
    float acc[8];
#pragma unroll
    for (int j = 0; j < 8; j++) acc[j] = 0.0f;
#pragma unroll
    for (int k = 0; k < FIN; k += 4) {
        float w0 = Ws[(k + 0) * HID + c];
        float w1 = Ws[(k + 1) * HID + c];
        float w2 = Ws[(k + 2) * HID + c];
        float w3 = Ws[(k + 3) * HID + c];
#pragma unroll
        for (int j = 0; j < 8; j++) {
            float4 xv = *(const float4*)&xs[rbase + 4 * j][k];
            acc[j] += xv.x * w0 + xv.y * w1 + xv.z * w2 + xv.w * w3;
        }
    }
#pragma unroll
    for (int j = 0; j < 8; j++) {
        int r = row0 + rbase + 4 * j;
        if (r < n)
            g_h1h[r * HID + c] = __float2half(acc[j] * rsqrtf((float)g_cnt[r] + 1.0f));
    }
}

// convert uint4 (8 halves) into 8 floats accumulated
__device__ __forceinline__ void acc_half8(float* a, uint4 u) {
    float2 f;
    f = __half22float2(*(__half2*)&u.x); a[0] += f.x; a[1] += f.y;
    f = __half22float2(*(__half2*)&u.y); a[2] += f.x; a[3] += f.y;
    f = __half22float2(*(__half2*)&u.z); a[4] += f.x; a[5] += f.y;
    f = __half22float2(*(__half2*)&u.w); a[6] += f.x; a[7] += f.y;
}

// ---- agg layer 1: warp/node; 4 edges/iter (h=lane>>3), 8 halves/lane ----
__global__ void k_agg1(const float* __restrict__ b1, int n) {
    int node = blockIdx.x * 8 + (threadIdx.x >> 5);
    if (node >= n) return;
    int lane = threadIdx.x & 31;
    int h = lane >> 3;   // edge slot 0..3
    int q = lane & 7;    // 8-half chunk within 64-half row
    int start = (node > 0) ? g_pos[node - 1] : 0;
    int end = g_pos[node];
    float a[8];
#pragma unroll
    for (int i = 0; i < 8; i++) a[i] = 0.0f;
    const __half* H = g_h1h;
    int e = start + h;
    for (; e + 4 < end; e += 8) {   // edges e and e+4 for this slot
        int s0 = g_esrc[e];
        int s1 = g_esrc[e + 4];
        uint4 u0 = *(const uint4*)(H + s0 * HID + q * 8);
        uint4 u1 = *(const uint4*)(H + s1 * HID + q * 8);
        acc_half8(a, u0);
        acc_half8(a, u1);
    }
    for (; e < end; e += 4) {
        int s = g_esrc[e];
        uint4 u = *(const uint4*)(H + s * HID + q * 8);
        acc_half8(a, u);
    }
#pragma unroll
    for (int i = 0; i < 8; i++) {
        a[i] += __shfl_xor_sync(0xffffffffu, a[i], 8);
        a[i] += __shfl_xor_sync(0xffffffffu, a[i], 16);
    }
    if (h == 0) {   // lanes 0..7, q = lane
        float di = rsqrtf((float)(end - start) + 1.0f);
        float self[8];
        {
            uint4 u = *(const uint4*)(H + node * HID + q * 8);
            float2 f;
            f = __half22float2(*(__half2*)&u.x); self[0] = f.x; self[1] = f.y;
            f = __half22float2(*(__half2*)&u.y); self[2] = f.x; self[3] = f.y;
            f = __half22float2(*(__half2*)&u.z); self[4] = f.x; self[5] = f.y;
            f = __half22float2(*(__half2*)&u.w); self[6] = f.x; self[7] = f.y;
        }
        float4 o0, o1;
        float* op = &o0.x;
#pragma unroll
        for (int i = 0; i < 8; i++) {
            float v = (a[i] + self[i]) * di + b1[q * 8 + i];
            ((i < 4) ? (&o0.x)[i] : (&o1.x)[i - 4]) = fmaxf(v, 0.0f);
        }
        (void)op;
        *(float4*)(g_act1 + node * HID + q * 8)     = o0;
        *(float4*)(g_act1 + node * HID + q * 8 + 4) = o1;
    }
}

// ---- GEMM2: h2h[r,:] = fp16( (act1[r,:] @ W2) * dinv[r] ) ----
__global__ void k_gemm2(const float* __restrict__ W, int n) {
    __shared__ float Ws[HID * NCLS];
    __shared__ __align__(16) float xs[64][HID + 4];
    int t = threadIdx.x;
    for (int i = t; i < HID * NCLS; i += 256) Ws[i] = W[i];
    int row0 = blockIdx.x * 64;
    for (int i = t; i < (64 * HID) / 4; i += 256) {
        int r = i >> 4, k4 = i & 15;
        int gr = row0 + r;
        float4 v = make_float4(0.f, 0.f, 0.f, 0.f);
        if (gr < n) v = *(const float4*)(g_act1 + gr * HID + k4 * 4);
        *(float4*)&xs[r][k4 * 4] = v;
    }
    __syncthreads();

    int c = t & 15;
    int rt = t >> 4;
    float acc[4];
#pragma unroll
    for (int j = 0; j < 4; j++) acc[j] = 0.0f;
#pragma unroll
    for (int k = 0; k < HID; k += 4) {
        float w0 = Ws[(k + 0) * NCLS + c];
        float w1 = Ws[(k + 1) * NCLS + c];
        float w2 = Ws[(k + 2) * NCLS + c];
        float w3 = Ws[(k + 3) * NCLS + c];
#pragma unroll
        for (int j = 0; j < 4; j++) {
            float4 xv = *(const float4*)&xs[rt + 16 * j][k];
            acc[j] += xv.x * w0 + xv.y * w1 + xv.z * w2 + xv.w * w3;
        }
    }
#pragma unroll
    for (int j = 0; j < 4; j++) {
        int r = row0 + rt + 16 * j;
        if (r < n)
            g_h2h[r * NCLS + c] = __float2half(acc[j] * rsqrtf((float)g_cnt[r] + 1.0f));
    }
}

// ---- agg layer 2: warp/node; 16 edges/iter (g=lane>>1), 8 halves/lane ----
__global__ void k_agg2(const float* __restrict__ b2, float* __restrict__ out, int n) {
    int node = blockIdx.x * 8 + (threadIdx.x >> 5);
    if (node >= n) return;
    int lane = threadIdx.x & 31;
    int g = lane >> 1;   // edge slot 0..15
    int q = lane & 1;    // which 8-half chunk of 16-half row
    int start = (node > 0) ? g_pos[node - 1] : 0;
    int end = g_pos[node];
    float a[8];
#pragma unroll
    for (int i = 0; i < 8; i++) a[i] = 0.0f;
    const __half* H = g_h2h;
    int e = start + g;
    for (; e + 16 < end; e += 32) {  // edges e and e+16
        int s0 = g_esrc[e];
        int s1 = g_esrc[e + 16];
        uint4 u0 = *(const uint4*)(H + s0 * NCLS + q * 8);
        uint4 u1 = *(const uint4*)(H + s1 * NCLS + q * 8);
        acc_half8(a, u0);
        acc_half8(a, u1);
    }
    for (; e < end; e += 16) {
        int s = g_esrc[e];
        uint4 u = *(const uint4*)(H + s * NCLS + q * 8);
        acc_half8(a, u);
    }
#pragma unroll
    for (int i = 0; i < 8; i++) {
        a[i] += __shfl_xor_sync(0xffffffffu, a[i], 2);
        a[i] += __shfl_xor_sync(0xffffffffu, a[i], 4);
        a[i] += __shfl_xor_sync(0xffffffffu, a[i], 8);
        a[i] += __shfl_xor_sync(0xffffffffu, a[i], 16);
    }
    if (g == 0) {   // lanes 0,1
        float di = rsqrtf((float)(end - start) + 1.0f);
        float self[8];
        {
            uint4 u = *(const uint4*)(H + node * NCLS + q * 8);
            float2 f;
            f = __half22float2(*(__half2*)&u.x); self[0] = f.x; self[1] = f.y;
            f = __half22float2(*(__half2*)&u.y); self[2] = f.x; self[3] = f.y;
            f = __half22float2(*(__half2*)&u.z); self[4] = f.x; self[5] = f.y;
            f = __half22float2(*(__half2*)&u.w); self[6] = f.x; self[7] = f.y;
        }
        float4 o0, o1;
#pragma unroll
        for (int i = 0; i < 8; i++) {
            float v = (a[i] + self[i]) * di + b2[q * 8 + i];
            ((i < 4) ? (&o0.x)[i] : (&o1.x)[i - 4]) = v;
        }
        *(float4*)(out + node * NCLS + q * 8)     = o0;
        *(float4*)(out + node * NCLS + q * 8 + 4) = o1;
    }
}

extern "C" void kernel_launch(void* const* d_in, const int* in_sizes, int n_in,
                              void* d_out, int out_size) {
    const float* x = (const float*)d_in[0];
    const void* ei = d_in[1];
    const float* W1 = (const float*)d_in[2];
    const float* b1 = (const float*)d_in[3];
    const float* W2 = (const float*)d_in[4];
    const float* b2 = (const float*)d_in[5];
    float* out = (float*)d_out;

    int n = in_sizes[0] / FIN;   // 50000
    int E = in_sizes[1] / 2;     // 800000

    k_zero_detect<<<(n + 255) / 256, 256>>>((const long long*)ei, n);
    k_hist<<<(E / 4 + 255) / 256, 256>>>(ei, E);
    k_scan<<<1, 1024>>>(n);
    k_fill<<<(E / 4 + 255) / 256, 256>>>(ei, E);

    k_gemm1<<<(n + 31) / 32, 256>>>(x, W1, n);
    k_agg1<<<(n + 7) / 8, 256>>>(b1, n);

    k_gemm2<<<(n + 63) / 64, 256>>>(W2, n);
    k_agg2<<<(n + 7) / 8, 256>>>(b2, out, n);
}